// round 15
// baseline (speedup 1.0000x reference)
#include <cuda_runtime.h>
#include <cuda_bf16.h>
#include <cstdint>

#define B_  8
#define C_  256
#define N_  2048
#define D_  32
#define BJ  64
#define NT  (N_ / BJ)
#define LOG2E 1.4426950408889634f

// ---------------------------------------------------------------------------
// Device-global scratch (allocation-free)
// ---------------------------------------------------------------------------
__device__ __nv_bfloat16  g_xt [(size_t)B_ * N_ * C_];   // x^T  (B,N,C) bf16
__device__ __nv_bfloat16  g_qt [(size_t)B_ * N_ * D_];   // q^T  (B,N,D) bf16, scaled by log2e
__device__ __nv_bfloat16  g_kt [(size_t)B_ * N_ * D_];   // k^T  (B,N,D) bf16
__device__ __nv_bfloat16  g_vbf[(size_t)B_ * C_ * N_];   // v    (B,C,N) bf16
__device__ __nv_bfloat16  g_wall[320 * C_];              // {wv; wq*log2e; wk} bf16
__device__ float          g_ball[320];                   // {bv; bq*log2e; bk}

// ---------------------------------------------------------------------------
// PTX helpers (legacy mma path: compute_100 PTX target)
// ---------------------------------------------------------------------------
__device__ __forceinline__ uint32_t smem_u32(const void* p) {
    uint32_t a;
    asm("{ .reg .u64 t; cvta.to.shared.u64 t, %1; cvt.u32.u64 %0, t; }"
        : "=r"(a) : "l"(p));
    return a;
}
__device__ __forceinline__ void ldm_x4(uint32_t* r, uint32_t addr) {
    asm volatile("ldmatrix.sync.aligned.m8n8.x4.shared.b16 {%0,%1,%2,%3}, [%4];\n"
        : "=r"(r[0]), "=r"(r[1]), "=r"(r[2]), "=r"(r[3]) : "r"(addr));
}
__device__ __forceinline__ void mma_bf16(float* d, const uint32_t* a, const uint32_t* b) {
    asm volatile(
        "mma.sync.aligned.m16n8k16.row.col.f32.bf16.bf16.f32 "
        "{%0,%1,%2,%3},{%4,%5,%6,%7},{%8,%9},{%0,%1,%2,%3};\n"
        : "+f"(d[0]), "+f"(d[1]), "+f"(d[2]), "+f"(d[3])
        : "r"(a[0]), "r"(a[1]), "r"(a[2]), "r"(a[3]), "r"(b[0]), "r"(b[1]));
}
__device__ __forceinline__ uint32_t packbf2(float a, float b) {
    __nv_bfloat162 h = __floats2bfloat162_rn(a, b);
    return *(uint32_t*)&h;
}
__device__ __forceinline__ float ex2(float x) {
    float y;
    asm("ex2.approx.f32 %0, %1;" : "=f"(y) : "f"(x));
    return y;
}
#define CP_ASYNC16(saddr, gptr) \
    asm volatile("cp.async.cg.shared.global [%0], [%1], 16;\n" :: "r"(saddr), "l"(gptr))
#define CP_COMMIT() asm volatile("cp.async.commit_group;\n")
#define CP_WAIT0()  asm volatile("cp.async.wait_group 0;\n")
#define CP_WAIT1()  asm volatile("cp.async.wait_group 1;\n")
#define BAR_SYNC(id, cnt) \
    asm volatile("bar.sync %0, %1;" :: "r"(id), "r"(cnt) : "memory")

#define SMS 40   // 32 data + 8 pad bf16
#define VMS 72   // 64 data + 8 pad bf16
#define QKS 80   // q/k staging stride

// prep dispatch: pack_x 4096 | pack_wall 80 | bias 1
#define PREP_PACKX  4096
#define PREP_PACKW  (PREP_PACKX + 80)
#define PREP_TOTAL  (PREP_PACKW + 1)

// ---------------------------------------------------------------------------
// prep: pack_x (transpose+bf16), pack_wall (wv|wq*log2e|wk), biases
// ---------------------------------------------------------------------------
__global__ __launch_bounds__(256) void prep_kernel(
    const float* __restrict__ x,
    const float* __restrict__ wq, const float* __restrict__ bq,
    const float* __restrict__ wk, const float* __restrict__ bk,
    const float* __restrict__ wv, const float* __restrict__ bv,
    __nv_bfloat16* __restrict__ xt, __nv_bfloat16* __restrict__ wall,
    float* __restrict__ ball)
{
    __shared__ float t[32][33];
    const int bid = blockIdx.x, tid = threadIdx.x;

    if (bid < PREP_PACKX) {
        const int n0 = (bid & 63) * 32, c0 = ((bid >> 6) & 7) * 32, b = bid >> 9;
        #pragma unroll
        for (int r = 0; r < 4; r++) {
            const int c = (tid >> 5) + r * 8;
            t[c][tid & 31] = x[((size_t)b * C_ + c0 + c) * N_ + n0 + (tid & 31)];
        }
        __syncthreads();
        #pragma unroll
        for (int r = 0; r < 4; r++) {
            const int n = (tid >> 5) + r * 8;
            xt[((size_t)b * N_ + n0 + n) * C_ + c0 + (tid & 31)] =
                __float2bfloat16(t[tid & 31][n]);
        }
        return;
    }
    if (bid < PREP_PACKW) {
        const int blk = bid - PREP_PACKX;
        const float* src = (blk < 64) ? (wv + blk * 1024)
                         : (blk < 72) ? (wq + (blk - 64) * 1024)
                                      : (wk + (blk - 72) * 1024);
        const float scl = (blk >= 64 && blk < 72) ? LOG2E : 1.0f;
        const int off = tid * 4;
        const float4 w4 = *(const float4*)(src + off);
        __nv_bfloat16* dst = wall + blk * 1024 + off;
        *(__nv_bfloat162*)(dst)     = __floats2bfloat162_rn(w4.x * scl, w4.y * scl);
        *(__nv_bfloat162*)(dst + 2) = __floats2bfloat162_rn(w4.z * scl, w4.w * scl);
        return;
    }
    if (tid < 256) ball[tid] = bv[tid];
    if (tid < 32) {
        ball[256 + tid] = bq[tid] * LOG2E;
        ball[288 + tid] = bk[tid];
    }
}

// ---------------------------------------------------------------------------
// projall: [320 x 2048 x 256] bf16 GEMM per batch (R13 version, 10.2us).
//   rows 0-255 -> v ; rows 256-287 -> q^T ; rows 288-319 -> k^T
// ---------------------------------------------------------------------------
__global__ __launch_bounds__(256) void projall_tc(
    const __nv_bfloat16* __restrict__ wall, const float* __restrict__ ball,
    const __nv_bfloat16* __restrict__ xt,
    __nv_bfloat16* __restrict__ v, __nv_bfloat16* __restrict__ qt,
    __nv_bfloat16* __restrict__ kt)
{
    __shared__ __align__(16) __nv_bfloat16 sm[2 * 64 * SMS + 2 * 128 * SMS];
    const int b = blockIdx.z, m0 = blockIdx.y * 64, n0 = blockIdx.x * 128;
    const int tid = threadIdx.x, lane = tid & 31, warp = tid >> 5;
    const int islice = warp >> 1, half = warp & 1;
    const int rrow = lane & 15, chalf = (lane >> 4) << 3;
    const uint32_t sAb = smem_u32(sm);
    const uint32_t sBb = sAb + 2 * 64 * SMS * 2;

    const int arow = tid >> 2, c8 = (tid & 3) * 8;
    const __nv_bfloat16* A  = wall + (size_t)(m0 + arow) * C_ + c8;

    float acc[8][4] = {};

    {
        CP_ASYNC16(sAb + (uint32_t)((arow * SMS + c8) * 2), A);
        #pragma unroll
        for (int p = 0; p < 2; p++) {
            const int idx = tid + p * 256, br = idx >> 2, bs = (idx & 3) * 8;
            CP_ASYNC16(sBb + (uint32_t)((br * SMS + bs) * 2),
                       xt + ((size_t)b * N_ + n0 + br) * C_ + bs);
        }
        CP_COMMIT();
    }
    #pragma unroll 1
    for (int it = 0; it < 8; it++) {
        CP_WAIT0(); __syncthreads();
        if (it < 7) {
            const int st = (it + 1) & 1, j0 = (it + 1) * 32;
            CP_ASYNC16(sAb + (uint32_t)((st * 64 * SMS + arow * SMS + c8) * 2), A + j0);
            #pragma unroll
            for (int p = 0; p < 2; p++) {
                const int idx = tid + p * 256, br = idx >> 2, bs = (idx & 3) * 8;
                CP_ASYNC16(sBb + (uint32_t)((st * 128 * SMS + br * SMS + bs) * 2),
                           xt + ((size_t)b * N_ + n0 + br) * C_ + j0 + bs);
            }
            CP_COMMIT();
        }
        const uint32_t sA = sAb + (uint32_t)((it & 1) * 64 * SMS * 2);
        const uint32_t sB = sBb + (uint32_t)((it & 1) * 128 * SMS * 2);
        #pragma unroll
        for (int ks2 = 0; ks2 < 2; ks2++) {
            const int ks = ks2 * 16;
            uint32_t af[4];
            ldm_x4(af, sA + (uint32_t)(((islice * 16 + rrow) * SMS + ks + chalf) * 2));
            #pragma unroll
            for (int cg = 0; cg < 4; cg++) {
                uint32_t bf4[4];
                ldm_x4(bf4, sB + (uint32_t)(((half * 64 + cg * 16 + rrow) * SMS
                                             + ks + chalf) * 2));
                #pragma unroll
                for (int np = 0; np < 2; np++) {
                    uint32_t bb[2] = { bf4[np], bf4[np + 2] };
                    mma_bf16(acc[cg * 2 + np], af, bb);
                }
            }
        }
        __syncthreads();
    }

    const int mrow = m0 + islice * 16 + (lane >> 2);
    const float bl0 = ball[mrow], bl8 = ball[mrow + 8];

    if (m0 < 256) {
        #pragma unroll
        for (int t8 = 0; t8 < 8; t8++) {
            const int n = n0 + half * 64 + t8 * 8 + (lane & 3) * 2;
            *(__nv_bfloat162*)(v + ((size_t)b * C_ + mrow) * N_ + n) =
                __floats2bfloat162_rn(acc[t8][0] + bl0, acc[t8][1] + bl0);
            *(__nv_bfloat162*)(v + ((size_t)b * C_ + mrow + 8) * N_ + n) =
                __floats2bfloat162_rn(acc[t8][2] + bl8, acc[t8][3] + bl8);
        }
    } else {
        __nv_bfloat16* qk = sm;
        const int mloc = islice * 16 + (lane >> 2);
        #pragma unroll
        for (int t8 = 0; t8 < 8; t8++) {
            const int nl = half * 64 + t8 * 8 + (lane & 3) * 2;
            qk[(size_t)nl * QKS + mloc]           = __float2bfloat16(acc[t8][0] + bl0);
            qk[(size_t)(nl + 1) * QKS + mloc]     = __float2bfloat16(acc[t8][1] + bl0);
            qk[(size_t)nl * QKS + mloc + 8]       = __float2bfloat16(acc[t8][2] + bl8);
            qk[(size_t)(nl + 1) * QKS + mloc + 8] = __float2bfloat16(acc[t8][3] + bl8);
        }
        __syncthreads();
        #pragma unroll
        for (int rep = 0; rep < 4; rep++) {
            const int idx = rep * 256 + tid;
            const int row = idx >> 3, ci = idx & 7;
            const int m8 = ci * 8;
            __nv_bfloat16* dst = (m8 < 32) ? qt : kt;
            const uint4 val = *(const uint4*)&qk[(size_t)row * QKS + m8];
            *(uint4*)(dst + ((size_t)b * N_ + n0 + row) * D_ + (m8 & 31)) = val;
        }
    }
}

// ---------------------------------------------------------------------------
// Flash attention — software-pipelined P: O(t) consumes P computed at t-1,
// S(t+1)/exp/STS run in the same iteration, pair-BAR only at iteration end.
// Block = 64 i-rows x 128 c, 8 warps = 4 i-slices x 2 halves. P double-buffer.
// ---------------------------------------------------------------------------
#define KOFF_B  (64 * SMS * 2)
#define VOFF_B  (KOFF_B + 3 * 64 * SMS * 2)
#define POFF_B  (VOFF_B + 3 * 128 * VMS * 2)
#define PPITCH  (16 * VMS * 2)
#define FL_SMEM (POFF_B + 8 * PPITCH)   // 2 P buffers x 4 pairs = 94208

__global__ __launch_bounds__(256, 2) void flash_tc(
    const __nv_bfloat16* __restrict__ qt, const __nv_bfloat16* __restrict__ kt,
    const __nv_bfloat16* __restrict__ v, const float* __restrict__ x,
    const float* __restrict__ gamma, float* __restrict__ out)
{
    extern __shared__ __align__(16) char smem_raw[];
    __shared__ float l_sm[2][64];

    const int b  = blockIdx.z;
    const int i0 = blockIdx.y * 64;
    const int c0 = blockIdx.x * 128;
    const int tid = threadIdx.x, lane = tid & 31, warp = tid >> 5;
    const int islice = warp >> 1;
    const int half   = warp & 1;
    const int rrow = lane & 15, chalf = (lane >> 4) << 3;

    const __nv_bfloat16* Qg = qt + ((size_t)b * N_ + i0) * D_;
    const __nv_bfloat16* Kg = kt + (size_t)b * N_ * D_;
    const __nv_bfloat16* Vg = v  + ((size_t)b * C_ + c0) * N_;

    const uint32_t sQa = smem_u32(smem_raw);
    const uint32_t sKa = sQa + KOFF_B;
    const uint32_t sVa = sQa + VOFF_B;
    // P buffers: [pbuf][islice] tiles of 16 x VMS bf16
    const uint32_t sP0 = sQa + POFF_B + (uint32_t)islice * PPITCH;
    const uint32_t sP1 = sP0 + 4 * PPITCH;

    // prologue: group0 = {Q, K0, V0}, group1 = {K1, V1}
    {
        const int r = tid >> 2, s = (tid & 3) * 8;
        CP_ASYNC16(sQa + (uint32_t)((r * SMS + s) * 2), Qg + (size_t)r * D_ + s);
        CP_ASYNC16(sKa + (uint32_t)((r * SMS + s) * 2), Kg + (size_t)r * D_ + s);
        #pragma unroll
        for (int p = 0; p < 4; p++) {
            const int idx = tid + p * 256, vr = idx >> 3, vs = (idx & 7) * 8;
            CP_ASYNC16(sVa + (uint32_t)((vr * VMS + vs) * 2), Vg + (size_t)vr * N_ + vs);
        }
        CP_COMMIT();
        CP_ASYNC16(sKa + (uint32_t)((64 * SMS + r * SMS + s) * 2),
                   Kg + (size_t)(BJ + r) * D_ + s);
        #pragma unroll
        for (int p = 0; p < 4; p++) {
            const int idx = tid + p * 256, vr = idx >> 3, vs = (idx & 7) * 8;
            CP_ASYNC16(sVa + (uint32_t)((128 * VMS + vr * VMS + vs) * 2),
                       Vg + (size_t)vr * N_ + BJ + vs);
        }
        CP_COMMIT();
    }

    float accO[8][4] = {};
    float l0 = 0.f, l1 = 0.f;
    uint32_t qf[2][4];

    // ---- prologue compute: S(0) -> P[0] ----
    CP_WAIT1(); __syncthreads();   // tile 0 resident
    ldm_x4(qf[0], sQa + (uint32_t)(((islice * 16 + rrow) * SMS + 0  + chalf) * 2));
    ldm_x4(qf[1], sQa + (uint32_t)(((islice * 16 + rrow) * SMS + 16 + chalf) * 2));
    {
        float accS[4][4] = {};
        #pragma unroll
        for (int jt2 = 0; jt2 < 2; jt2++) {
            const int jt = half * 2 + jt2;
            uint32_t b0[4], b1[4];
            ldm_x4(b0, sKa + (uint32_t)(((jt * 16 + rrow) * SMS + 0  + chalf) * 2));
            ldm_x4(b1, sKa + (uint32_t)(((jt * 16 + rrow) * SMS + 16 + chalf) * 2));
            #pragma unroll
            for (int np = 0; np < 2; np++) {
                uint32_t bb0[2] = { b0[np], b0[np + 2] };
                uint32_t bb1[2] = { b1[np], b1[np + 2] };
                mma_bf16(accS[jt2 * 2 + np], qf[0], bb0);
                mma_bf16(accS[jt2 * 2 + np], qf[1], bb1);
            }
        }
        #pragma unroll
        for (int t4 = 0; t4 < 4; t4++) {
            const float e0 = ex2(accS[t4][0]);
            const float e1 = ex2(accS[t4][1]);
            const float e2 = ex2(accS[t4][2]);
            const float e3 = ex2(accS[t4][3]);
            l0 += e0 + e1; l1 += e2 + e3;
            const int jcol = half * 32 + t4 * 8 + (lane & 3) * 2;
            const int r0 = lane >> 2;
            *(uint32_t*)(smem_raw + (sP0 - sQa) + (r0 * VMS + jcol) * 2) = packbf2(e0, e1);
            *(uint32_t*)(smem_raw + (sP0 - sQa) + ((r0 + 8) * VMS + jcol) * 2) = packbf2(e2, e3);
        }
    }
    BAR_SYNC(1 + islice, 64);

    // ---- pipelined mainloop ----
    #pragma unroll 1
    for (int t = 0; t < NT; t++) {
        if (t + 1 < NT) { CP_WAIT0(); }
        __syncthreads();
        if (t + 2 < NT) {
            const int bf = (t + 2) % 3, j1 = (t + 2) * BJ;
            const int r = tid >> 2, s = (tid & 3) * 8;
            CP_ASYNC16(sKa + (uint32_t)((bf * 64 * SMS + r * SMS + s) * 2),
                       Kg + (size_t)(j1 + r) * D_ + s);
            #pragma unroll
            for (int p = 0; p < 4; p++) {
                const int idx = tid + p * 256, vr = idx >> 3, vs = (idx & 7) * 8;
                CP_ASYNC16(sVa + (uint32_t)((bf * 128 * VMS + vr * VMS + vs) * 2),
                           Vg + (size_t)vr * N_ + j1 + vs);
            }
            CP_COMMIT();
        }

        // ---- O(t): P[t&1] x V(t) (depends only on last iteration's BAR) ----
        {
            const uint32_t vb = sVa + (uint32_t)((t % 3) * 128 * VMS * 2);
            const uint32_t pa = (t & 1) ? sP1 : sP0;
            #pragma unroll
            for (int ks = 0; ks < 4; ks++) {
                uint32_t pfk[4];
                ldm_x4(pfk, pa + (uint32_t)((rrow * VMS + ks * 16 + chalf) * 2));
                #pragma unroll
                for (int cg = 0; cg < 4; cg++) {
                    uint32_t vb4[4];
                    ldm_x4(vb4, vb + (uint32_t)(((half * 64 + cg * 16 + rrow) * VMS
                                                 + ks * 16 + chalf) * 2));
                    #pragma unroll
                    for (int np = 0; np < 2; np++) {
                        uint32_t bb[2] = { vb4[np], vb4[np + 2] };
                        mma_bf16(accO[cg * 2 + np], pfk, bb);
                    }
                }
            }
        }

        // ---- S(t+1) -> P[(t+1)&1] ----
        if (t + 1 < NT) {
            const uint32_t kb = sKa + (uint32_t)(((t + 1) % 3) * 64 * SMS * 2);
            float accS[4][4] = {};
            #pragma unroll
            for (int jt2 = 0; jt2 < 2; jt2++) {
                const int jt = half * 2 + jt2;
                uint32_t b0[4], b1[4];
                ldm_x4(b0, kb + (uint32_t)(((jt * 16 + rrow) * SMS + 0  + chalf) * 2));
                ldm_x4(b1, kb + (uint32_t)(((jt * 16 + rrow) * SMS + 16 + chalf) * 2));
                #pragma unroll
                for (int np = 0; np < 2; np++) {
                    uint32_t bb0[2] = { b0[np], b0[np + 2] };
                    uint32_t bb1[2] = { b1[np], b1[np + 2] };
                    mma_bf16(accS[jt2 * 2 + np], qf[0], bb0);
                    mma_bf16(accS[jt2 * 2 + np], qf[1], bb1);
                }
            }
            const uint32_t pw = ((t + 1) & 1) ? sP1 : sP0;
            #pragma unroll
            for (int t4 = 0; t4 < 4; t4++) {
                const float e0 = ex2(accS[t4][0]);
                const float e1 = ex2(accS[t4][1]);
                const float e2 = ex2(accS[t4][2]);
                const float e3 = ex2(accS[t4][3]);
                l0 += e0 + e1; l1 += e2 + e3;
                const int jcol = half * 32 + t4 * 8 + (lane & 3) * 2;
                const int r0 = lane >> 2;
                *(uint32_t*)(smem_raw + (pw - sQa) + (r0 * VMS + jcol) * 2) = packbf2(e0, e1);
                *(uint32_t*)(smem_raw + (pw - sQa) + ((r0 + 8) * VMS + jcol) * 2) = packbf2(e2, e3);
            }
        }
        BAR_SYNC(1 + islice, 64);
    }

    // ---- epilogue ----
    l0 += __shfl_xor_sync(0xFFFFFFFFu, l0, 1);
    l0 += __shfl_xor_sync(0xFFFFFFFFu, l0, 2);
    l1 += __shfl_xor_sync(0xFFFFFFFFu, l1, 1);
    l1 += __shfl_xor_sync(0xFFFFFFFFu, l1, 2);
    if ((lane & 3) == 0) {
        l_sm[half][islice * 16 + (lane >> 2)]     = l0;
        l_sm[half][islice * 16 + (lane >> 2) + 8] = l1;
    }
    __syncthreads();

    const int r = islice * 16 + (lane >> 2);
    const float il0 = 1.f / (l_sm[0][r] + l_sm[1][r]);
    const float il1 = 1.f / (l_sm[0][r + 8] + l_sm[1][r + 8]);
    const float g = *gamma;
    float* sO = (float*)smem_raw;

    #pragma unroll
    for (int t8 = 0; t8 < 8; t8++) {
        const int c = half * 64 + t8 * 8 + (lane & 3) * 2;
        const int i = islice * 16 + (lane >> 2);
        sO[(size_t)c * 68 + i]           = accO[t8][0] * il0;
        sO[(size_t)(c + 1) * 68 + i]     = accO[t8][1] * il0;
        sO[(size_t)c * 68 + i + 8]       = accO[t8][2] * il1;
        sO[(size_t)(c + 1) * 68 + i + 8] = accO[t8][3] * il1;
    }
    __syncthreads();
    #pragma unroll
    for (int rep = 0; rep < 8; rep++) {
        const int idx = rep * 256 + tid;
        const int c = idx >> 4, i4 = (idx & 15) * 4;
        const size_t base = ((size_t)b * C_ + c0 + c) * N_ + i0 + i4;
        const float4 xv = *(const float4*)(x + base);
        const float4 ov = *(const float4*)&sO[(size_t)c * 68 + i4];
        float4 o;
        o.x = g * ov.x + xv.x; o.y = g * ov.y + xv.y;
        o.z = g * ov.z + xv.z; o.w = g * ov.w + xv.w;
        *(float4*)(out + base) = o;
    }
}

// ---------------------------------------------------------------------------
// Launch
// ---------------------------------------------------------------------------
extern "C" void kernel_launch(void* const* d_in, const int* in_sizes, int n_in,
                              void* d_out, int out_size)
{
    const float* x     = (const float*)d_in[0];
    const float* wq    = (const float*)d_in[1];
    const float* bq    = (const float*)d_in[2];
    const float* wk    = (const float*)d_in[3];
    const float* bk    = (const float*)d_in[4];
    const float* wv    = (const float*)d_in[5];
    const float* bv    = (const float*)d_in[6];
    const float* gamma = (const float*)d_in[7];
    float* out = (float*)d_out;

    __nv_bfloat16 *pxt, *pqt, *pkt, *pvbf, *pwall;
    float* pball;
    cudaGetSymbolAddress((void**)&pxt,   g_xt);
    cudaGetSymbolAddress((void**)&pqt,   g_qt);
    cudaGetSymbolAddress((void**)&pkt,   g_kt);
    cudaGetSymbolAddress((void**)&pvbf,  g_vbf);
    cudaGetSymbolAddress((void**)&pwall, g_wall);
    cudaGetSymbolAddress((void**)&pball, g_ball);

    static bool attr_set = false;
    if (!attr_set) {
        cudaFuncSetAttribute(flash_tc, cudaFuncAttributeMaxDynamicSharedMemorySize,
                             FL_SMEM);
        attr_set = true;
    }

    prep_kernel<<<PREP_TOTAL, 256>>>(x, wq, bq, wk, bk, wv, bv, pxt, pwall, pball);
    projall_tc<<<dim3(N_ / 128, 5, B_), 256>>>(pwall, pball, pxt, pvbf, pqt, pkt);
    flash_tc<<<dim3(C_ / 128, N_ / 64, B_), 256, FL_SMEM>>>(pqt, pkt, pvbf, x, gamma, out);
}

// round 16
// speedup vs baseline: 1.0658x; 1.0658x over previous
#include <cuda_runtime.h>
#include <cuda_bf16.h>
#include <cstdint>

#define B_  8
#define C_  256
#define N_  2048
#define D_  32
#define BJ  64
#define NT  (N_ / BJ)
#define LOG2E 1.4426950408889634f

__device__ __nv_bfloat16  g_xt [(size_t)B_ * N_ * C_];
__device__ __nv_bfloat16  g_qt [(size_t)B_ * N_ * D_];
__device__ __nv_bfloat16  g_kt [(size_t)B_ * N_ * D_];
__device__ __nv_bfloat16  g_vbf[(size_t)B_ * C_ * N_];
__device__ __nv_bfloat16  g_wall[320 * C_];
__device__ float          g_ball[320];

__device__ __forceinline__ uint32_t smem_u32(const void* p) {
    uint32_t a;
    asm("{ .reg .u64 t; cvta.to.shared.u64 t, %1; cvt.u32.u64 %0, t; }"
        : "=r"(a) : "l"(p));
    return a;
}
__device__ __forceinline__ void ldm_x4(uint32_t* r, uint32_t addr) {
    asm volatile("ldmatrix.sync.aligned.m8n8.x4.shared.b16 {%0,%1,%2,%3}, [%4];\n"
        : "=r"(r[0]), "=r"(r[1]), "=r"(r[2]), "=r"(r[3]) : "r"(addr));
}
__device__ __forceinline__ void mma_bf16(float* d, const uint32_t* a, const uint32_t* b) {
    asm volatile(
        "mma.sync.aligned.m16n8k16.row.col.f32.bf16.bf16.f32 "
        "{%0,%1,%2,%3},{%4,%5,%6,%7},{%8,%9},{%0,%1,%2,%3};\n"
        : "+f"(d[0]), "+f"(d[1]), "+f"(d[2]), "+f"(d[3])
        : "r"(a[0]), "r"(a[1]), "r"(a[2]), "r"(a[3]), "r"(b[0]), "r"(b[1]));
}
__device__ __forceinline__ uint32_t packbf2(float a, float b) {
    __nv_bfloat162 h = __floats2bfloat162_rn(a, b);
    return *(uint32_t*)&h;
}
__device__ __forceinline__ float ex2(float x) {
    float y;
    asm("ex2.approx.f32 %0, %1;" : "=f"(y) : "f"(x));
    return y;
}
#define CP_ASYNC16(saddr, gptr) \
    asm volatile("cp.async.cg.shared.global [%0], [%1], 16;\n" :: "r"(saddr), "l"(gptr))
#define CP_COMMIT() asm volatile("cp.async.commit_group;\n")
#define CP_WAIT0()  asm volatile("cp.async.wait_group 0;\n")
#define CP_WAIT1()  asm volatile("cp.async.wait_group 1;\n")
#define BAR_SYNC(id, cnt) \
    asm volatile("bar.sync %0, %1;" :: "r"(id), "r"(cnt) : "memory")

#define SMS 40
#define VMS 72
#define QKS 80

#define PREP_PACKX  4096
#define PREP_PACKW  (PREP_PACKX + 80)
#define PREP_TOTAL  (PREP_PACKW + 1)

// ---------------------------------------------------------------------------
// prep (R13 verbatim)
// ---------------------------------------------------------------------------
__global__ __launch_bounds__(256) void prep_kernel(
    const float* __restrict__ x,
    const float* __restrict__ wq, const float* __restrict__ bq,
    const float* __restrict__ wk, const float* __restrict__ bk,
    const float* __restrict__ wv, const float* __restrict__ bv,
    __nv_bfloat16* __restrict__ xt, __nv_bfloat16* __restrict__ wall,
    float* __restrict__ ball)
{
    __shared__ float t[32][33];
    const int bid = blockIdx.x, tid = threadIdx.x;

    if (bid < PREP_PACKX) {
        const int n0 = (bid & 63) * 32, c0 = ((bid >> 6) & 7) * 32, b = bid >> 9;
        #pragma unroll
        for (int r = 0; r < 4; r++) {
            const int c = (tid >> 5) + r * 8;
            t[c][tid & 31] = x[((size_t)b * C_ + c0 + c) * N_ + n0 + (tid & 31)];
        }
        __syncthreads();
        #pragma unroll
        for (int r = 0; r < 4; r++) {
            const int n = (tid >> 5) + r * 8;
            xt[((size_t)b * N_ + n0 + n) * C_ + c0 + (tid & 31)] =
                __float2bfloat16(t[tid & 31][n]);
        }
        return;
    }
    if (bid < PREP_PACKW) {
        const int blk = bid - PREP_PACKX;
        const float* src = (blk < 64) ? (wv + blk * 1024)
                         : (blk < 72) ? (wq + (blk - 64) * 1024)
                                      : (wk + (blk - 72) * 1024);
        const float scl = (blk >= 64 && blk < 72) ? LOG2E : 1.0f;
        const int off = tid * 4;
        const float4 w4 = *(const float4*)(src + off);
        __nv_bfloat16* dst = wall + blk * 1024 + off;
        *(__nv_bfloat162*)(dst)     = __floats2bfloat162_rn(w4.x * scl, w4.y * scl);
        *(__nv_bfloat162*)(dst + 2) = __floats2bfloat162_rn(w4.z * scl, w4.w * scl);
        return;
    }
    if (tid < 256) ball[tid] = bv[tid];
    if (tid < 32) {
        ball[256 + tid] = bq[tid] * LOG2E;
        ball[288 + tid] = bk[tid];
    }
}

// ---------------------------------------------------------------------------
// projall (R13 verbatim)
// ---------------------------------------------------------------------------
__global__ __launch_bounds__(256) void projall_tc(
    const __nv_bfloat16* __restrict__ wall, const float* __restrict__ ball,
    const __nv_bfloat16* __restrict__ xt,
    __nv_bfloat16* __restrict__ v, __nv_bfloat16* __restrict__ qt,
    __nv_bfloat16* __restrict__ kt)
{
    __shared__ __align__(16) __nv_bfloat16 sm[2 * 64 * SMS + 2 * 128 * SMS];
    const int b = blockIdx.z, m0 = blockIdx.y * 64, n0 = blockIdx.x * 128;
    const int tid = threadIdx.x, lane = tid & 31, warp = tid >> 5;
    const int islice = warp >> 1, half = warp & 1;
    const int rrow = lane & 15, chalf = (lane >> 4) << 3;
    const uint32_t sAb = smem_u32(sm);
    const uint32_t sBb = sAb + 2 * 64 * SMS * 2;

    const int arow = tid >> 2, c8 = (tid & 3) * 8;
    const __nv_bfloat16* A  = wall + (size_t)(m0 + arow) * C_ + c8;

    float acc[8][4] = {};

    {
        CP_ASYNC16(sAb + (uint32_t)((arow * SMS + c8) * 2), A);
        #pragma unroll
        for (int p = 0; p < 2; p++) {
            const int idx = tid + p * 256, br = idx >> 2, bs = (idx & 3) * 8;
            CP_ASYNC16(sBb + (uint32_t)((br * SMS + bs) * 2),
                       xt + ((size_t)b * N_ + n0 + br) * C_ + bs);
        }
        CP_COMMIT();
    }
    #pragma unroll 1
    for (int it = 0; it < 8; it++) {
        CP_WAIT0(); __syncthreads();
        if (it < 7) {
            const int st = (it + 1) & 1, j0 = (it + 1) * 32;
            CP_ASYNC16(sAb + (uint32_t)((st * 64 * SMS + arow * SMS + c8) * 2), A + j0);
            #pragma unroll
            for (int p = 0; p < 2; p++) {
                const int idx = tid + p * 256, br = idx >> 2, bs = (idx & 3) * 8;
                CP_ASYNC16(sBb + (uint32_t)((st * 128 * SMS + br * SMS + bs) * 2),
                           xt + ((size_t)b * N_ + n0 + br) * C_ + j0 + bs);
            }
            CP_COMMIT();
        }
        const uint32_t sA = sAb + (uint32_t)((it & 1) * 64 * SMS * 2);
        const uint32_t sB = sBb + (uint32_t)((it & 1) * 128 * SMS * 2);
        #pragma unroll
        for (int ks2 = 0; ks2 < 2; ks2++) {
            const int ks = ks2 * 16;
            uint32_t af[4];
            ldm_x4(af, sA + (uint32_t)(((islice * 16 + rrow) * SMS + ks + chalf) * 2));
            #pragma unroll
            for (int cg = 0; cg < 4; cg++) {
                uint32_t bf4[4];
                ldm_x4(bf4, sB + (uint32_t)(((half * 64 + cg * 16 + rrow) * SMS
                                             + ks + chalf) * 2));
                #pragma unroll
                for (int np = 0; np < 2; np++) {
                    uint32_t bb[2] = { bf4[np], bf4[np + 2] };
                    mma_bf16(acc[cg * 2 + np], af, bb);
                }
            }
        }
        __syncthreads();
    }

    const int mrow = m0 + islice * 16 + (lane >> 2);
    const float bl0 = ball[mrow], bl8 = ball[mrow + 8];

    if (m0 < 256) {
        #pragma unroll
        for (int t8 = 0; t8 < 8; t8++) {
            const int n = n0 + half * 64 + t8 * 8 + (lane & 3) * 2;
            *(__nv_bfloat162*)(v + ((size_t)b * C_ + mrow) * N_ + n) =
                __floats2bfloat162_rn(acc[t8][0] + bl0, acc[t8][1] + bl0);
            *(__nv_bfloat162*)(v + ((size_t)b * C_ + mrow + 8) * N_ + n) =
                __floats2bfloat162_rn(acc[t8][2] + bl8, acc[t8][3] + bl8);
        }
    } else {
        __nv_bfloat16* qk = sm;
        const int mloc = islice * 16 + (lane >> 2);
        #pragma unroll
        for (int t8 = 0; t8 < 8; t8++) {
            const int nl = half * 64 + t8 * 8 + (lane & 3) * 2;
            qk[(size_t)nl * QKS + mloc]           = __float2bfloat16(acc[t8][0] + bl0);
            qk[(size_t)(nl + 1) * QKS + mloc]     = __float2bfloat16(acc[t8][1] + bl0);
            qk[(size_t)nl * QKS + mloc + 8]       = __float2bfloat16(acc[t8][2] + bl8);
            qk[(size_t)(nl + 1) * QKS + mloc + 8] = __float2bfloat16(acc[t8][3] + bl8);
        }
        __syncthreads();
        #pragma unroll
        for (int rep = 0; rep < 4; rep++) {
            const int idx = rep * 256 + tid;
            const int row = idx >> 3, ci = idx & 7;
            const int m8 = ci * 8;
            __nv_bfloat16* dst = (m8 < 32) ? qt : kt;
            const uint4 val = *(const uint4*)&qk[(size_t)row * QKS + m8];
            *(uint4*)(dst + ((size_t)b * N_ + n0 + row) * D_ + (m8 & 31)) = val;
        }
    }
}

// ---------------------------------------------------------------------------
// Flash attention — 512 threads, 64 i-rows x ALL 256 channels per block.
// 16 warps = 4 islices x 4 quads. Quad-warp computes 16i x 16j of S (its
// j-quarter), P assembled per-islice in smem (4 warps); O: warp handles its
// 64-c quarter, k=64. S-mma/exp/K-ldsm/STS halve chip-wide vs the 2-c-block
// layout. R13 intra-iteration ordering preserved.
// grid (N/64, B) = 256 blocks, 1 block/SM (140KB smem), 4 warps/SMSP.
// ---------------------------------------------------------------------------
#define F5_KOFF 5120                        // after Q (64*SMS*2)
#define F5_KBUF (64 * SMS * 2)              // 5120
#define F5_VOFF (F5_KOFF + 3 * F5_KBUF)     // 20480
#define F5_VBUF (256 * VMS * 2)             // 36864
#define F5_POFF (F5_VOFF + 3 * F5_VBUF)     // 131072
#define PPITCH  (16 * VMS * 2)              // 2304
#define F5_SMEM (F5_POFF + 4 * PPITCH)      // 140288

__global__ __launch_bounds__(512, 1) void flash_tc(
    const __nv_bfloat16* __restrict__ qt, const __nv_bfloat16* __restrict__ kt,
    const __nv_bfloat16* __restrict__ v, const float* __restrict__ x,
    const float* __restrict__ gamma, float* __restrict__ out)
{
    extern __shared__ __align__(16) char smem_raw[];
    __shared__ float l_red[4][64];

    const int b  = blockIdx.y;
    const int i0 = blockIdx.x * 64;
    const int tid = threadIdx.x, lane = tid & 31, warp = tid >> 5;
    const int islice = warp >> 2;    // 0..3: i-rows islice*16..+16
    const int quad   = warp & 3;     // j-quarter (S) / c-quarter (O)
    const int rrow = lane & 15, chalf = (lane >> 4) << 3;

    const __nv_bfloat16* Qg = qt + ((size_t)b * N_ + i0) * D_;
    const __nv_bfloat16* Kg = kt + (size_t)b * N_ * D_;
    const __nv_bfloat16* Vg = v  + (size_t)b * C_ * N_;

    const uint32_t sQa = smem_u32(smem_raw);
    const uint32_t sKa = sQa + F5_KOFF;
    const uint32_t sVa = sQa + F5_VOFF;
    const uint32_t sPa = sQa + F5_POFF + (uint32_t)islice * PPITCH;

    // prologue: group0 = {Q, K0, V0}, group1 = {K1, V1}
    {
        if (tid < 256) {
            const int r = tid >> 2, s = (tid & 3) * 8;
            CP_ASYNC16(sQa + (uint32_t)((r * SMS + s) * 2), Qg + (size_t)r * D_ + s);
            CP_ASYNC16(sKa + (uint32_t)((r * SMS + s) * 2), Kg + (size_t)r * D_ + s);
        }
        #pragma unroll
        for (int p = 0; p < 4; p++) {
            const int idx = tid + p * 512, vr = idx >> 3, vs = (idx & 7) * 8;
            CP_ASYNC16(sVa + (uint32_t)((vr * VMS + vs) * 2), Vg + (size_t)vr * N_ + vs);
        }
        CP_COMMIT();
        if (tid < 256) {
            const int r = tid >> 2, s = (tid & 3) * 8;
            CP_ASYNC16(sKa + (uint32_t)((F5_KBUF + r * SMS * 2 + s * 2)),
                       Kg + (size_t)(BJ + r) * D_ + s);
        }
        #pragma unroll
        for (int p = 0; p < 4; p++) {
            const int idx = tid + p * 512, vr = idx >> 3, vs = (idx & 7) * 8;
            CP_ASYNC16(sVa + (uint32_t)(F5_VBUF + (vr * VMS + vs) * 2),
                       Vg + (size_t)vr * N_ + BJ + vs);
        }
        CP_COMMIT();
    }

    float accO[8][4] = {};
    float l0 = 0.f, l1 = 0.f;
    uint32_t qf[2][4];

    #pragma unroll 1
    for (int t = 0; t < NT; t++) {
        CP_WAIT1(); __syncthreads();   // tile t resident; also protects P reuse
        if (t == 0) {
            ldm_x4(qf[0], sQa + (uint32_t)(((islice * 16 + rrow) * SMS + 0  + chalf) * 2));
            ldm_x4(qf[1], sQa + (uint32_t)(((islice * 16 + rrow) * SMS + 16 + chalf) * 2));
        }
        // prefetch tile t+2
        if (t + 2 < NT) {
            const int bf = (t + 2) % 3, j1 = (t + 2) * BJ;
            if (tid < 256) {
                const int r = tid >> 2, s = (tid & 3) * 8;
                CP_ASYNC16(sKa + (uint32_t)(bf * F5_KBUF + (r * SMS + s) * 2),
                           Kg + (size_t)(j1 + r) * D_ + s);
            }
            #pragma unroll
            for (int p = 0; p < 4; p++) {
                const int idx = tid + p * 512, vr = idx >> 3, vs = (idx & 7) * 8;
                CP_ASYNC16(sVa + (uint32_t)(bf * F5_VBUF + (vr * VMS + vs) * 2),
                           Vg + (size_t)vr * N_ + j1 + vs);
            }
        }
        CP_COMMIT();

        const uint32_t kb = sKa + (uint32_t)((t % 3) * F5_KBUF);
        const uint32_t vb = sVa + (uint32_t)((t % 3) * F5_VBUF);

        // ---- S = Q K^T : warp computes 16i x 16j (its j-quarter) ----
        float accS[2][4] = {};
        {
            uint32_t b0[4], b1[4];
            ldm_x4(b0, kb + (uint32_t)(((quad * 16 + rrow) * SMS + 0  + chalf) * 2));
            ldm_x4(b1, kb + (uint32_t)(((quad * 16 + rrow) * SMS + 16 + chalf) * 2));
            #pragma unroll
            for (int np = 0; np < 2; np++) {
                uint32_t bb0[2] = { b0[np], b0[np + 2] };
                uint32_t bb1[2] = { b1[np], b1[np + 2] };
                mma_bf16(accS[np], qf[0], bb0);
                mma_bf16(accS[np], qf[1], bb1);
            }
        }

        // ---- 2^S + store P quarter + partial l ----
        #pragma unroll
        for (int nt = 0; nt < 2; nt++) {
            const float e0 = ex2(accS[nt][0]);
            const float e1 = ex2(accS[nt][1]);
            const float e2 = ex2(accS[nt][2]);
            const float e3 = ex2(accS[nt][3]);
            l0 += e0 + e1; l1 += e2 + e3;
            const int jcol = quad * 16 + nt * 8 + (lane & 3) * 2;
            const int r0 = lane >> 2;
            *(uint32_t*)(smem_raw + (F5_POFF + islice * PPITCH) + (r0 * VMS + jcol) * 2)
                = packbf2(e0, e1);
            *(uint32_t*)(smem_raw + (F5_POFF + islice * PPITCH) + ((r0 + 8) * VMS + jcol) * 2)
                = packbf2(e2, e3);
        }
        BAR_SYNC(1 + islice, 128);   // islice group: P tile complete

        // ---- O += P V^T : warp 16i x 64c (its c-quarter), k=64 ----
        #pragma unroll
        for (int ks = 0; ks < 4; ks++) {
            uint32_t pfk[4];
            ldm_x4(pfk, sPa + (uint32_t)((rrow * VMS + ks * 16 + chalf) * 2));
            #pragma unroll
            for (int cg = 0; cg < 4; cg++) {
                uint32_t vb4[4];
                ldm_x4(vb4, vb + (uint32_t)(((quad * 64 + cg * 16 + rrow) * VMS
                                             + ks * 16 + chalf) * 2));
                #pragma unroll
                for (int np = 0; np < 2; np++) {
                    uint32_t bb[2] = { vb4[np], vb4[np + 2] };
                    mma_bf16(accO[cg * 2 + np], pfk, bb);
                }
            }
        }
    }

    // ---- epilogue: l quad-partials -> sum over 4 quads ----
    l0 += __shfl_xor_sync(0xFFFFFFFFu, l0, 1);
    l0 += __shfl_xor_sync(0xFFFFFFFFu, l0, 2);
    l1 += __shfl_xor_sync(0xFFFFFFFFu, l1, 1);
    l1 += __shfl_xor_sync(0xFFFFFFFFu, l1, 2);
    if ((lane & 3) == 0) {
        l_red[quad][islice * 16 + (lane >> 2)]     = l0;
        l_red[quad][islice * 16 + (lane >> 2) + 8] = l1;
    }
    __syncthreads();

    const int r = islice * 16 + (lane >> 2);
    const float il0 = 1.f / (l_red[0][r] + l_red[1][r] + l_red[2][r] + l_red[3][r]);
    const float il1 = 1.f / (l_red[0][r + 8] + l_red[1][r + 8] + l_red[2][r + 8] + l_red[3][r + 8]);
    const float g = *gamma;
    float* sO = (float*)smem_raw;   // 256c x 68i fp32 = 69632B (K/V dead)

    #pragma unroll
    for (int t8 = 0; t8 < 8; t8++) {
        const int c = quad * 64 + t8 * 8 + (lane & 3) * 2;
        const int i = islice * 16 + (lane >> 2);
        sO[(size_t)c * 68 + i]           = accO[t8][0] * il0;
        sO[(size_t)(c + 1) * 68 + i]     = accO[t8][1] * il0;
        sO[(size_t)c * 68 + i + 8]       = accO[t8][2] * il1;
        sO[(size_t)(c + 1) * 68 + i + 8] = accO[t8][3] * il1;
    }
    __syncthreads();
    #pragma unroll
    for (int rep = 0; rep < 8; rep++) {
        const int idx = rep * 512 + tid;
        const int c = idx >> 4, i4 = (idx & 15) * 4;
        const size_t base = ((size_t)b * C_ + c) * N_ + i0 + i4;
        const float4 xv = *(const float4*)(x + base);
        const float4 ov = *(const float4*)&sO[(size_t)c * 68 + i4];
        float4 o;
        o.x = g * ov.x + xv.x; o.y = g * ov.y + xv.y;
        o.z = g * ov.z + xv.z; o.w = g * ov.w + xv.w;
        *(float4*)(out + base) = o;
    }
}

// ---------------------------------------------------------------------------
// Launch
// ---------------------------------------------------------------------------
extern "C" void kernel_launch(void* const* d_in, const int* in_sizes, int n_in,
                              void* d_out, int out_size)
{
    const float* x     = (const float*)d_in[0];
    const float* wq    = (const float*)d_in[1];
    const float* bq    = (const float*)d_in[2];
    const float* wk    = (const float*)d_in[3];
    const float* bk    = (const float*)d_in[4];
    const float* wv    = (const float*)d_in[5];
    const float* bv    = (const float*)d_in[6];
    const float* gamma = (const float*)d_in[7];
    float* out = (float*)d_out;

    __nv_bfloat16 *pxt, *pqt, *pkt, *pvbf, *pwall;
    float* pball;
    cudaGetSymbolAddress((void**)&pxt,   g_xt);
    cudaGetSymbolAddress((void**)&pqt,   g_qt);
    cudaGetSymbolAddress((void**)&pkt,   g_kt);
    cudaGetSymbolAddress((void**)&pvbf,  g_vbf);
    cudaGetSymbolAddress((void**)&pwall, g_wall);
    cudaGetSymbolAddress((void**)&pball, g_ball);

    static bool attr_set = false;
    if (!attr_set) {
        cudaFuncSetAttribute(flash_tc, cudaFuncAttributeMaxDynamicSharedMemorySize,
                             F5_SMEM);
        attr_set = true;
    }

    prep_kernel<<<PREP_TOTAL, 256>>>(x, wq, bq, wk, bk, wv, bv, pxt, pwall, pball);
    projall_tc<<<dim3(N_ / 128, 5, B_), 256>>>(pwall, pball, pxt, pvbf, pqt, pkt);
    flash_tc<<<dim3(N_ / 64, B_), 512, F5_SMEM>>>(pqt, pkt, pvbf, x, gamma, out);
}